// round 1
// baseline (speedup 1.0000x reference)
#include <cuda_runtime.h>
#include <cstdint>

#define VOCAB 256
#define D 512
#define A 64
#define BB 8
#define LL 2048
#define LN_EPS 1e-5f

// ---------------- scratch (device globals; no allocations) ----------------
__device__ float g_h[VOCAB * D];          // h per token value
__device__ float g_q[VOCAB * A];
__device__ float g_k[VOCAB * A];
__device__ float g_gate[VOCAB];
__device__ float g_vprob[VOCAB * VOCAB];  // softmax(tied-head logits)
__device__ float g_score[VOCAB * VOCAB];  // q·k^T / 8
__device__ int   g_cnt[BB * VOCAB];       // per-batch prefix histogram
__device__ float g_AT[BB * VOCAB * VOCAB]; // attn value table
__device__ float g_LM[BB * VOCAB * VOCAB]; // log(mixed) table

// ---------------- reduction helpers ----------------
__device__ __forceinline__ float warpSum(float v) {
    #pragma unroll
    for (int o = 16; o > 0; o >>= 1) v += __shfl_xor_sync(0xFFFFFFFFu, v, o);
    return v;
}
__device__ __forceinline__ float warpMax(float v) {
    #pragma unroll
    for (int o = 16; o > 0; o >>= 1) v = fmaxf(v, __shfl_xor_sync(0xFFFFFFFFu, v, o));
    return v;
}
// 256-thread block reductions, shared buffer sh[8]
__device__ __forceinline__ float blockSum256(float v, float* sh) {
    int w = threadIdx.x >> 5, l = threadIdx.x & 31;
    v = warpSum(v);
    if (l == 0) sh[w] = v;
    __syncthreads();
    if (w == 0) {
        float x = (l < 8) ? sh[l] : 0.f;
        x = warpSum(x);
        if (l == 0) sh[0] = x;
    }
    __syncthreads();
    float r = sh[0];
    __syncthreads();
    return r;
}
__device__ __forceinline__ float blockMax256(float v, float* sh) {
    int w = threadIdx.x >> 5, l = threadIdx.x & 31;
    v = warpMax(v);
    if (l == 0) sh[w] = v;
    __syncthreads();
    if (w == 0) {
        float x = (l < 8) ? sh[l] : -1e30f;
        x = warpMax(x);
        if (l == 0) sh[0] = x;
    }
    __syncthreads();
    float r = sh[0];
    __syncthreads();
    return r;
}

// ---------------- k1a: h = LN(LN(embed[v])) ----------------
__global__ void k_h(const float* __restrict__ E,
                    const float* __restrict__ eg, const float* __restrict__ eb,
                    const float* __restrict__ fg, const float* __restrict__ fb) {
    int v = blockIdx.x, tid = threadIdx.x;
    __shared__ float red[8];
    float a = E[v * D + tid];
    float b = E[v * D + 256 + tid];
    float mu = blockSum256(a + b, red) * (1.f / D);
    float d0 = a - mu, d1 = b - mu;
    float var = blockSum256(d0 * d0 + d1 * d1, red) * (1.f / D);
    float inv = rsqrtf(var + LN_EPS);
    float h0 = d0 * inv * eg[tid] + eb[tid];
    float h1 = d1 * inv * eg[tid + 256] + eb[tid + 256];
    mu = blockSum256(h0 + h1, red) * (1.f / D);
    d0 = h0 - mu; d1 = h1 - mu;
    var = blockSum256(d0 * d0 + d1 * d1, red) * (1.f / D);
    inv = rsqrtf(var + LN_EPS);
    g_h[v * D + tid]       = d0 * inv * fg[tid] + fb[tid];
    g_h[v * D + 256 + tid] = d1 * inv * fg[tid + 256] + fb[tid + 256];
}

// ---------------- k1b: vprob / q / k / gate tables (8 v-rows per block) ----
__global__ void k_tab(const float* __restrict__ E,
                      const float* __restrict__ qw, const float* __restrict__ qb,
                      const float* __restrict__ kw, const float* __restrict__ kb,
                      const float* __restrict__ gw, const float* __restrict__ gb) {
    int tid = threadIdx.x, w = tid >> 5, l = tid & 31;
    int v0 = blockIdx.x * 8;
    __shared__ float hs[8][D];
    __shared__ float slog[8][VOCAB];
    for (int i = tid; i < 8 * D; i += 256) ((float*)hs)[i] = g_h[v0 * D + i];
    __syncthreads();

    // tied-head logits: warp w handles vocab columns u = w, w+8, ...
    for (int u = w; u < VOCAB; u += 8) {
        float e[16];
        #pragma unroll
        for (int j = 0; j < 16; j++) e[j] = E[u * D + l + 32 * j];
        #pragma unroll
        for (int r = 0; r < 8; r++) {
            float s = 0.f;
            #pragma unroll
            for (int j = 0; j < 16; j++) s += e[j] * hs[r][l + 32 * j];
            s = warpSum(s);
            if (l == 0) slog[r][u] = s;
        }
    }
    // q (64) / k (64) / gate (1) projections
    for (int o = w; o < 129; o += 8) {
        const float* wrow; float bias;
        if (o < 64)       { wrow = qw + o * D;        bias = qb[o]; }
        else if (o < 128) { wrow = kw + (o - 64) * D; bias = kb[o - 64]; }
        else              { wrow = gw;                bias = gb[0]; }
        float e[16];
        #pragma unroll
        for (int j = 0; j < 16; j++) e[j] = wrow[l + 32 * j];
        #pragma unroll
        for (int r = 0; r < 8; r++) {
            float s = 0.f;
            #pragma unroll
            for (int j = 0; j < 16; j++) s += e[j] * hs[r][l + 32 * j];
            s = warpSum(s);
            if (l == 0) {
                if (o < 64)       g_q[(v0 + r) * A + o] = s + bias;
                else if (o < 128) g_k[(v0 + r) * A + (o - 64)] = s + bias;
                else              g_gate[v0 + r] = 1.f / (1.f + expf(-(s + bias)));
            }
        }
    }
    __syncthreads();
    // softmax over vocab: warp w owns row w
    {
        int r = w;
        float vals[8];
        float m = -1e30f;
        #pragma unroll
        for (int j = 0; j < 8; j++) { vals[j] = slog[r][l + 32 * j]; m = fmaxf(m, vals[j]); }
        m = warpMax(m);
        float ss = 0.f;
        #pragma unroll
        for (int j = 0; j < 8; j++) { vals[j] = expf(vals[j] - m); ss += vals[j]; }
        ss = warpSum(ss);
        float invs = 1.f / ss;
        #pragma unroll
        for (int j = 0; j < 8; j++) g_vprob[(v0 + r) * VOCAB + l + 32 * j] = vals[j] * invs;
    }
}

// ---------------- k2: score[qv][kv] = q·k / sqrt(64) ----------------
__global__ void k_score() {
    int qv = blockIdx.x, tid = threadIdx.x, w = tid >> 5, l = tid & 31;
    __shared__ float qs[A];
    if (tid < A) qs[tid] = g_q[qv * A + tid];
    __syncthreads();
    for (int kv = w; kv < VOCAB; kv += 8) {
        float s = qs[l] * g_k[kv * A + l] + qs[l + 32] * g_k[kv * A + l + 32];
        s = warpSum(s);
        if (l == 0) g_score[qv * VOCAB + kv] = s * 0.125f;
    }
}

// ---------------- k3a: per-batch prefix histogram ----------------
__global__ void k_hist(const int* __restrict__ tokens, const int* __restrict__ plen) {
    int b = blockIdx.x, tid = threadIdx.x;
    __shared__ int c[VOCAB];
    c[tid] = 0;
    __syncthreads();
    int P = plen[b];
    for (int s = tid; s < LL; s += 256) {
        int tk = tokens[b * LL + s];
        if (s < P && tk != 0) atomicAdd(&c[tk & 255], 1);
    }
    __syncthreads();
    g_cnt[b * VOCAB + tid] = c[tid];
}

// ---------------- k3b: AT (attn values) and LM (log mixed) tables ----------
__global__ void k_atlm() {
    int qv = blockIdx.x, b = blockIdx.y, v = threadIdx.x;
    __shared__ float red[8];
    float s = g_score[qv * VOCAB + v];
    float c = (float)g_cnt[b * VOCAB + v];
    float m = blockMax256(c > 0.f ? s : -1e30f, red);
    float e = expf(s - m);
    float Z = blockSum256(c * e, red);
    float at = e / Z;
    if (v == 0) at = 0.f;               // PAD positions are masked
    int off = (b * VOCAB + qv) * VOCAB + v;
    g_AT[off] = at;
    float gt = g_gate[qv];
    float p = g_vprob[qv * VOCAB + v];
    float mixed = gt * p + (1.f - gt) * (c * at);   // copy_dist = count * attn-val
    g_LM[off] = logf(fmaxf(mixed, 1e-12f));
}

// ---------------- k4: streaming writer (the HBM-bound part) ----------------
__global__ void __launch_bounds__(256)
k_write(const int* __restrict__ tokens, const int* __restrict__ plen,
        float* __restrict__ out, int has_gate, int has_attn) {
    int b = blockIdx.y, t0 = blockIdx.x * 8, tid = threadIdx.x;
    __shared__ __align__(16) int toks[LL];
    __shared__ float lut[8][VOCAB];
    __shared__ int qvs[8];

    const int4* tg = (const int4*)(tokens + b * LL);
    int4* ts = (int4*)toks;
    ts[tid] = tg[tid];
    ts[tid + 256] = tg[tid + 256];
    __syncthreads();
    if (tid < 8) qvs[tid] = toks[t0 + tid] & 255;
    __syncthreads();
    #pragma unroll
    for (int j = 0; j < 8; j++)
        lut[j][tid] = g_AT[(b * VOCAB + qvs[j]) * VOCAB + tid];

    int P = plen[b];
    float* out_lm   = out;
    float* out_gate = out + (size_t)BB * LL * VOCAB;
    float* out_attn = out_gate + (size_t)BB * LL;

    if (has_gate && tid < 8) out_gate[b * LL + t0 + tid] = g_gate[qvs[tid]];
    __syncthreads();

    #pragma unroll
    for (int j = 0; j < 8; j++) {
        int t = t0 + j, qv = qvs[j];
        out_lm[((size_t)(b * LL + t)) * VOCAB + tid] = g_LM[(b * VOCAB + qv) * VOCAB + tid];
        if (has_attn) {
            float4* orow = (float4*)(out_attn + ((size_t)(b * LL + t)) * LL);
            #pragma unroll
            for (int k2 = 0; k2 < 2; k2++) {
                int sb = (k2 * 256 + tid) * 4;
                int4 tk = *(const int4*)&toks[sb];
                float4 o;
                o.x = (sb + 0 < P) ? lut[j][tk.x & 255] : 0.f;
                o.y = (sb + 1 < P) ? lut[j][tk.y & 255] : 0.f;
                o.z = (sb + 2 < P) ? lut[j][tk.z & 255] : 0.f;
                o.w = (sb + 3 < P) ? lut[j][tk.w & 255] : 0.f;
                orow[k2 * 256 + tid] = o;
            }
        }
    }
}

// ---------------- launch ----------------
extern "C" void kernel_launch(void* const* d_in, const int* in_sizes, int n_in,
                              void* d_out, int out_size) {
    const int*   tokens = (const int*)d_in[0];
    const int*   plen   = (const int*)d_in[1];
    const float* E      = (const float*)d_in[2];
    const float* en_g   = (const float*)d_in[3];
    const float* en_b   = (const float*)d_in[4];
    const float* fn_g   = (const float*)d_in[5];
    const float* fn_b   = (const float*)d_in[6];
    const float* q_w    = (const float*)d_in[7];
    const float* q_b    = (const float*)d_in[8];
    const float* k_w    = (const float*)d_in[9];
    const float* k_b    = (const float*)d_in[10];
    const float* g_w    = (const float*)d_in[11];
    const float* g_b    = (const float*)d_in[12];

    const long long lm_sz   = (long long)BB * LL * VOCAB;       // 4,194,304
    const long long gate_sz = (long long)BB * LL;               // 16,384
    const long long attn_sz = (long long)BB * LL * LL;          // 33,554,432
    int has_gate = (out_size >= lm_sz + gate_sz) ? 1 : 0;
    int has_attn = (out_size >= lm_sz + gate_sz + attn_sz) ? 1 : 0;

    k_h    <<<VOCAB, 256>>>(E, en_g, en_b, fn_g, fn_b);
    k_tab  <<<VOCAB / 8, 256>>>(E, q_w, q_b, k_w, k_b, g_w, g_b);
    k_score<<<VOCAB, 256>>>();
    k_hist <<<BB, 256>>>(tokens, plen);
    k_atlm <<<dim3(VOCAB, BB), 256>>>();
    k_write<<<dim3(LL / 8, BB), 256>>>(tokens, plen, (float*)d_out, has_gate, has_attn);
}

// round 2
// speedup vs baseline: 1.7095x; 1.7095x over previous
#include <cuda_runtime.h>
#include <cstdint>

#define VOCAB 256
#define D 512
#define A 64
#define BB 8
#define LL 2048
#define LN_EPS 1e-5f

// ---------------- scratch (device globals; no allocations) ----------------
__device__ float g_h[VOCAB * D];            // h per token value
__device__ float g_q[VOCAB * A];
__device__ float g_k[VOCAB * A];
__device__ float g_gate[VOCAB];
__device__ float g_logit[VOCAB * VOCAB];    // tied-head logits
__device__ int   g_cntp[BB * 8 * VOCAB];    // per-batch per-chunk histogram partials
__device__ float g_AT[BB * VOCAB * VOCAB];  // attn value table
__device__ float g_LM[BB * VOCAB * VOCAB];  // log(mixed) table

// ---------------- reduction helpers ----------------
__device__ __forceinline__ float warpSum(float v) {
    #pragma unroll
    for (int o = 16; o > 0; o >>= 1) v += __shfl_xor_sync(0xFFFFFFFFu, v, o);
    return v;
}
__device__ __forceinline__ float warpMax(float v) {
    #pragma unroll
    for (int o = 16; o > 0; o >>= 1) v = fmaxf(v, __shfl_xor_sync(0xFFFFFFFFu, v, o));
    return v;
}
__device__ __forceinline__ float blockSum256(float v, float* sh) {
    int w = threadIdx.x >> 5, l = threadIdx.x & 31;
    v = warpSum(v);
    if (l == 0) sh[w] = v;
    __syncthreads();
    if (w == 0) {
        float x = (l < 8) ? sh[l] : 0.f;
        x = warpSum(x);
        if (l == 0) sh[0] = x;
    }
    __syncthreads();
    float r = sh[0];
    __syncthreads();
    return r;
}
__device__ __forceinline__ float blockMax256(float v, float* sh) {
    int w = threadIdx.x >> 5, l = threadIdx.x & 31;
    v = warpMax(v);
    if (l == 0) sh[w] = v;
    __syncthreads();
    if (w == 0) {
        float x = (l < 8) ? sh[l] : -1e30f;
        x = warpMax(x);
        if (l == 0) sh[0] = x;
    }
    __syncthreads();
    float r = sh[0];
    __syncthreads();
    return r;
}

// ---------------- k_h: h = LN(LN(embed[v])), one block per vocab value ----
__global__ void k_h(const float* __restrict__ E,
                    const float* __restrict__ eg, const float* __restrict__ eb,
                    const float* __restrict__ fg, const float* __restrict__ fb) {
    int v = blockIdx.x, tid = threadIdx.x;
    __shared__ float red[8];
    float a = E[v * D + tid];
    float b = E[v * D + 256 + tid];
    float mu = blockSum256(a + b, red) * (1.f / D);
    float d0 = a - mu, d1 = b - mu;
    float var = blockSum256(d0 * d0 + d1 * d1, red) * (1.f / D);
    float inv = rsqrtf(var + LN_EPS);
    float h0 = d0 * inv * eg[tid] + eb[tid];
    float h1 = d1 * inv * eg[tid + 256] + eb[tid + 256];
    mu = blockSum256(h0 + h1, red) * (1.f / D);
    d0 = h0 - mu; d1 = h1 - mu;
    var = blockSum256(d0 * d0 + d1 * d1, red) * (1.f / D);
    inv = rsqrtf(var + LN_EPS);
    g_h[v * D + tid]       = d0 * inv * fg[tid] + fb[tid];
    g_h[v * D + 256 + tid] = d1 * inv * fg[tid + 256] + fb[tid + 256];
}

// ---------------- k_proj: logits + q + k + gate, wide grid ----------------
// grid = (13 col-groups of 32, 32 row-groups of 8 vocab rows)
// output column o: [0,256) logits, [256,320) q, [320,384) k, 384 gate
__global__ void __launch_bounds__(256)
k_proj(const float* __restrict__ E,
       const float* __restrict__ qw, const float* __restrict__ qb,
       const float* __restrict__ kw, const float* __restrict__ kb,
       const float* __restrict__ gw, const float* __restrict__ gb) {
    int tid = threadIdx.x, w = tid >> 5, l = tid & 31;
    int v0 = blockIdx.y * 8;
    int obase = blockIdx.x * 32;
    __shared__ float hs[8][D];
    for (int i = tid; i < 8 * D; i += 256) ((float*)hs)[i] = g_h[v0 * D + i];
    __syncthreads();

    #pragma unroll
    for (int i = 0; i < 4; i++) {
        int o = obase + w + 8 * i;
        if (o > 384) continue;
        const float* wrow; float bias;
        if (o < 256)      { wrow = E + o * D;          bias = 0.f; }
        else if (o < 320) { wrow = qw + (o - 256) * D; bias = qb[o - 256]; }
        else if (o < 384) { wrow = kw + (o - 320) * D; bias = kb[o - 320]; }
        else              { wrow = gw;                 bias = gb[0]; }
        float e[16];
        #pragma unroll
        for (int j = 0; j < 16; j++) e[j] = wrow[l + 32 * j];
        #pragma unroll
        for (int r = 0; r < 8; r++) {
            float s = 0.f;
            #pragma unroll
            for (int j = 0; j < 16; j++) s += e[j] * hs[r][l + 32 * j];
            s = warpSum(s);
            if (l == 0) {
                int v = v0 + r;
                if (o < 256)      g_logit[v * VOCAB + o] = s;
                else if (o < 320) g_q[v * A + (o - 256)] = s + bias;
                else if (o < 384) g_k[v * A + (o - 320)] = s + bias;
                else              g_gate[v] = 1.f / (1.f + expf(-(s + bias)));
            }
        }
    }
}

// ---------------- k_hist: partial histograms, 64 blocks --------------------
__global__ void k_hist(const int* __restrict__ tokens, const int* __restrict__ plen) {
    int chunk = blockIdx.x, b = blockIdx.y, tid = threadIdx.x;
    __shared__ int c[VOCAB];
    c[tid] = 0;
    __syncthreads();
    int s = chunk * 256 + tid;
    int P = plen[b];
    int tk = tokens[b * LL + s];
    if (s < P && tk != 0) atomicAdd(&c[tk & 255], 1);
    __syncthreads();
    g_cntp[(b * 8 + chunk) * VOCAB + tid] = c[tid];
}

// ---------------- k_mix: softmax(logits) + scores + AT/LM tables ----------
__global__ void __launch_bounds__(256)
k_mix() {
    int qv = blockIdx.x, tid = threadIdx.x, w = tid >> 5, l = tid & 31;
    __shared__ float red[8];
    __shared__ float sc[VOCAB];
    __shared__ float qs[A];

    // vocab softmax for this qv row
    float lo = g_logit[qv * VOCAB + tid];
    float m = blockMax256(lo, red);
    float e = expf(lo - m);
    float Z = blockSum256(e, red);
    float p = e / Z;

    if (tid < A) qs[tid] = g_q[qv * A + tid];
    __syncthreads();
    // scores: warp-reduced dots against all k rows
    for (int kv = w; kv < VOCAB; kv += 8) {
        float s = qs[l] * g_k[kv * A + l] + qs[l + 32] * g_k[kv * A + l + 32];
        s = warpSum(s);
        if (l == 0) sc[kv] = s * 0.125f;
    }
    __syncthreads();

    float gt = g_gate[qv];
    float s_v = sc[tid];
    #pragma unroll
    for (int b = 0; b < BB; b++) {
        int c = 0;
        #pragma unroll
        for (int ch = 0; ch < 8; ch++) c += g_cntp[(b * 8 + ch) * VOCAB + tid];
        float cf = (float)c;
        float m2 = blockMax256(c > 0 ? s_v : -1e30f, red);
        float e2 = expf(s_v - m2);
        float Z2 = blockSum256(cf * e2, red);
        float at = e2 / Z2;
        if (tid == 0) at = 0.f;   // PAD column masked
        int off = (b * VOCAB + qv) * VOCAB + tid;
        g_AT[off] = at;
        float mixed = gt * p + (1.f - gt) * (cf * at);
        g_LM[off] = logf(fmaxf(mixed, 1e-12f));
    }
}

// ---------------- k_write: streaming writer (HBM-bound) -------------------
__global__ void __launch_bounds__(256)
k_write(const int* __restrict__ tokens, const int* __restrict__ plen,
        float* __restrict__ out, int has_gate, int has_attn) {
    int b = blockIdx.y, t0 = blockIdx.x * 16, tid = threadIdx.x;
    __shared__ __align__(16) int toks[LL];
    __shared__ float lut[16][VOCAB];
    __shared__ int qvs[16];

    const int4* tg = (const int4*)(tokens + b * LL);
    int4* ts = (int4*)toks;
    ts[tid] = tg[tid];
    ts[tid + 256] = tg[tid + 256];
    __syncthreads();
    if (tid < 16) qvs[tid] = toks[t0 + tid] & 255;
    __syncthreads();
    #pragma unroll
    for (int j = 0; j < 16; j++)
        lut[j][tid] = g_AT[(b * VOCAB + qvs[j]) * VOCAB + tid];

    int P = plen[b];
    float* out_lm   = out;
    float* out_gate = out + (size_t)BB * LL * VOCAB;
    float* out_attn = out_gate + (size_t)BB * LL;

    if (has_gate && tid < 16) out_gate[b * LL + t0 + tid] = g_gate[qvs[tid]];

    // log-mixed rows: 4 rows at a time, 64 threads/row, float4
    {
        int rj = tid >> 6, l64 = tid & 63;
        #pragma unroll
        for (int jb = 0; jb < 16; jb += 4) {
            int j = jb + rj;
            int qv = qvs[j];
            float4 v = ((const float4*)(g_LM + ((size_t)(b * VOCAB + qv)) * VOCAB))[l64];
            ((float4*)(out_lm + ((size_t)(b * LL + t0 + j)) * VOCAB))[l64] = v;
        }
    }
    __syncthreads();

    if (has_attn) {
        #pragma unroll
        for (int j = 0; j < 16; j++) {
            float4* orow = (float4*)(out_attn + ((size_t)(b * LL + t0 + j)) * LL);
            #pragma unroll
            for (int k2 = 0; k2 < 2; k2++) {
                int sb = (k2 * 256 + tid) * 4;
                int4 tk = *(const int4*)&toks[sb];
                float4 o;
                o.x = (sb + 0 < P) ? lut[j][tk.x & 255] : 0.f;
                o.y = (sb + 1 < P) ? lut[j][tk.y & 255] : 0.f;
                o.z = (sb + 2 < P) ? lut[j][tk.z & 255] : 0.f;
                o.w = (sb + 3 < P) ? lut[j][tk.w & 255] : 0.f;
                orow[k2 * 256 + tid] = o;
            }
        }
    }
}

// ---------------- launch ----------------
extern "C" void kernel_launch(void* const* d_in, const int* in_sizes, int n_in,
                              void* d_out, int out_size) {
    const int*   tokens = (const int*)d_in[0];
    const int*   plen   = (const int*)d_in[1];
    const float* E      = (const float*)d_in[2];
    const float* en_g   = (const float*)d_in[3];
    const float* en_b   = (const float*)d_in[4];
    const float* fn_g   = (const float*)d_in[5];
    const float* fn_b   = (const float*)d_in[6];
    const float* q_w    = (const float*)d_in[7];
    const float* q_b    = (const float*)d_in[8];
    const float* k_w    = (const float*)d_in[9];
    const float* k_b    = (const float*)d_in[10];
    const float* g_w    = (const float*)d_in[11];
    const float* g_b    = (const float*)d_in[12];

    const long long lm_sz   = (long long)BB * LL * VOCAB;
    const long long gate_sz = (long long)BB * LL;
    const long long attn_sz = (long long)BB * LL * LL;
    int has_gate = (out_size >= lm_sz + gate_sz) ? 1 : 0;
    int has_attn = (out_size >= lm_sz + gate_sz + attn_sz) ? 1 : 0;

    k_h   <<<VOCAB, 256>>>(E, en_g, en_b, fn_g, fn_b);
    k_hist<<<dim3(8, BB), 256>>>(tokens, plen);
    k_proj<<<dim3(13, 32), 256>>>(E, q_w, q_b, k_w, k_b, g_w, g_b);
    k_mix <<<VOCAB, 256>>>();
    k_write<<<dim3(LL / 16, BB), 256>>>(tokens, plen, (float*)d_out, has_gate, has_attn);
}

// round 3
// speedup vs baseline: 1.8013x; 1.0537x over previous
#include <cuda_runtime.h>
#include <cstdint>

#define VOCAB 256
#define D 512
#define A 64
#define BB 8
#define LL 2048
#define LN_EPS 1e-5f

// ---------------- scratch (device globals; no allocations) ----------------
__device__ float g_h[VOCAB * D];
__device__ float g_q[VOCAB * A];
__device__ float g_k[VOCAB * A];
__device__ float g_gate[VOCAB];
__device__ float g_logit[VOCAB * VOCAB];
__device__ int   g_cntp[BB * 8 * VOCAB];
__device__ float g_AT[BB * VOCAB * VOCAB];
__device__ float g_LM[BB * VOCAB * VOCAB];

// ---------------- reduction helpers ----------------
__device__ __forceinline__ float warpSum(float v) {
    #pragma unroll
    for (int o = 16; o > 0; o >>= 1) v += __shfl_xor_sync(0xFFFFFFFFu, v, o);
    return v;
}
__device__ __forceinline__ float warpMax(float v) {
    #pragma unroll
    for (int o = 16; o > 0; o >>= 1) v = fmaxf(v, __shfl_xor_sync(0xFFFFFFFFu, v, o));
    return v;
}
__device__ __forceinline__ float blockSum256(float v, float* sh) {
    int w = threadIdx.x >> 5, l = threadIdx.x & 31;
    v = warpSum(v);
    if (l == 0) sh[w] = v;
    __syncthreads();
    if (w == 0) {
        float x = (l < 8) ? sh[l] : 0.f;
        x = warpSum(x);
        if (l == 0) sh[0] = x;
    }
    __syncthreads();
    float r = sh[0];
    __syncthreads();
    return r;
}
__device__ __forceinline__ float blockMax256(float v, float* sh) {
    int w = threadIdx.x >> 5, l = threadIdx.x & 31;
    v = warpMax(v);
    if (l == 0) sh[w] = v;
    __syncthreads();
    if (w == 0) {
        float x = (l < 8) ? sh[l] : -1e30f;
        x = warpMax(x);
        if (l == 0) sh[0] = x;
    }
    __syncthreads();
    float r = sh[0];
    __syncthreads();
    return r;
}

// ---------------- k_h: h = LN(LN(embed[v])) ----------------
__global__ void k_h(const float* __restrict__ E,
                    const float* __restrict__ eg, const float* __restrict__ eb,
                    const float* __restrict__ fg, const float* __restrict__ fb) {
    int v = blockIdx.x, tid = threadIdx.x;
    __shared__ float red[8];
    float a = E[v * D + tid];
    float b = E[v * D + 256 + tid];
    float mu = blockSum256(a + b, red) * (1.f / D);
    float d0 = a - mu, d1 = b - mu;
    float var = blockSum256(d0 * d0 + d1 * d1, red) * (1.f / D);
    float inv = rsqrtf(var + LN_EPS);
    float h0 = d0 * inv * eg[tid] + eb[tid];
    float h1 = d1 * inv * eg[tid + 256] + eb[tid + 256];
    mu = blockSum256(h0 + h1, red) * (1.f / D);
    d0 = h0 - mu; d1 = h1 - mu;
    var = blockSum256(d0 * d0 + d1 * d1, red) * (1.f / D);
    inv = rsqrtf(var + LN_EPS);
    g_h[v * D + tid]       = d0 * inv * fg[tid] + fb[tid];
    g_h[v * D + 256 + tid] = d1 * inv * fg[tid + 256] + fb[tid + 256];
}

// ---------------- k_proj: logits + q + k + gate, wide grid ----------------
__global__ void __launch_bounds__(256)
k_proj(const float* __restrict__ E,
       const float* __restrict__ qw, const float* __restrict__ qb,
       const float* __restrict__ kw, const float* __restrict__ kb,
       const float* __restrict__ gw, const float* __restrict__ gb) {
    int tid = threadIdx.x, w = tid >> 5, l = tid & 31;
    int v0 = blockIdx.y * 8;
    int obase = blockIdx.x * 32;
    __shared__ float hs[8][D];
    for (int i = tid; i < 8 * D; i += 256) ((float*)hs)[i] = g_h[v0 * D + i];
    __syncthreads();

    #pragma unroll
    for (int i = 0; i < 4; i++) {
        int o = obase + w + 8 * i;
        if (o > 384) continue;
        const float* wrow; float bias;
        if (o < 256)      { wrow = E + o * D;          bias = 0.f; }
        else if (o < 320) { wrow = qw + (o - 256) * D; bias = qb[o - 256]; }
        else if (o < 384) { wrow = kw + (o - 320) * D; bias = kb[o - 320]; }
        else              { wrow = gw;                 bias = gb[0]; }
        float e[16];
        #pragma unroll
        for (int j = 0; j < 16; j++) e[j] = wrow[l + 32 * j];
        #pragma unroll
        for (int r = 0; r < 8; r++) {
            float s = 0.f;
            #pragma unroll
            for (int j = 0; j < 16; j++) s += e[j] * hs[r][l + 32 * j];
            s = warpSum(s);
            if (l == 0) {
                int v = v0 + r;
                if (o < 256)      g_logit[v * VOCAB + o] = s;
                else if (o < 320) g_q[v * A + (o - 256)] = s + bias;
                else if (o < 384) g_k[v * A + (o - 320)] = s + bias;
                else              g_gate[v] = 1.f / (1.f + __expf(-(s + bias)));
            }
        }
    }
}

// ---------------- k_hist: partial histograms, 64 blocks --------------------
__global__ void k_hist(const int* __restrict__ tokens, const int* __restrict__ plen) {
    int chunk = blockIdx.x, b = blockIdx.y, tid = threadIdx.x;
    __shared__ int c[VOCAB];
    c[tid] = 0;
    __syncthreads();
    int s = chunk * 256 + tid;
    int P = plen[b];
    int tk = tokens[b * LL + s];
    if (s < P && tk != 0) atomicAdd(&c[tk & 255], 1);
    __syncthreads();
    g_cntp[(b * 8 + chunk) * VOCAB + tid] = c[tid];
}

// ---------------- k_mix: softmax + scores + AT/LM (warp-per-batch) --------
__global__ void __launch_bounds__(256)
k_mix() {
    int qv = blockIdx.x, tid = threadIdx.x, w = tid >> 5, l = tid & 31;
    __shared__ float red[8];
    __shared__ float sc[VOCAB];
    __shared__ float sp[VOCAB];
    __shared__ float qs[A];
    __shared__ float scnt[BB][VOCAB];

    // pre-sum histogram partials into smem (once per block)
    for (int i = tid; i < BB * VOCAB; i += 256) {
        int b = i >> 8, v = i & 255;
        int c = 0;
        #pragma unroll
        for (int ch = 0; ch < 8; ch++) c += g_cntp[(b * 8 + ch) * VOCAB + v];
        scnt[b][v] = (float)c;
    }

    // vocab softmax for this qv row
    float lo = g_logit[qv * VOCAB + tid];
    float m = blockMax256(lo, red);
    float e = __expf(lo - m);
    float Z = blockSum256(e, red);
    sp[tid] = e / Z;

    if (tid < A) qs[tid] = g_q[qv * A + tid];
    __syncthreads();
    // scores: warp-reduced dots against all k rows
    for (int kv = w; kv < VOCAB; kv += 8) {
        float s = qs[l] * g_k[kv * A + l] + qs[l + 32] * g_k[kv * A + l + 32];
        s = warpSum(s);
        if (l == 0) sc[kv] = s * 0.125f;
    }
    __syncthreads();

    // warp w owns batch w: zero barriers from here on
    {
        int b = w;
        float gt = g_gate[qv];
        float sv[8], cf[8], pv[8];
        float mx = -1e30f;
        #pragma unroll
        for (int j = 0; j < 8; j++) {
            int v = l + 32 * j;
            sv[j] = sc[v];
            cf[j] = scnt[b][v];
            pv[j] = sp[v];
            mx = fmaxf(mx, cf[j] > 0.f ? sv[j] : -1e30f);
        }
        mx = warpMax(mx);
        float ex[8], z = 0.f;
        #pragma unroll
        for (int j = 0; j < 8; j++) {
            ex[j] = __expf(sv[j] - mx);
            z += cf[j] * ex[j];
        }
        z = warpSum(z);
        float invz = __frcp_rn(z);
        size_t base = ((size_t)b * VOCAB + qv) * VOCAB;
        #pragma unroll
        for (int j = 0; j < 8; j++) {
            int v = l + 32 * j;
            float at = ex[j] * invz;
            if (v == 0) at = 0.f;     // PAD column masked
            g_AT[base + v] = at;
            float mixed = gt * pv[j] + (1.f - gt) * (cf[j] * at);
            g_LM[base + v] = __logf(fmaxf(mixed, 1e-12f));
        }
    }
}

// ---------------- k_write: streaming writer (HBM-bound) -------------------
__global__ void __launch_bounds__(256)
k_write(const int* __restrict__ tokens, const int* __restrict__ plen,
        float* __restrict__ out, int has_gate, int has_attn) {
    int b = blockIdx.y, t0 = blockIdx.x * 16, tid = threadIdx.x;
    __shared__ __align__(16) int toks[LL];
    __shared__ float lut[16][VOCAB];
    __shared__ int qvs[16];

    const int4* tg = (const int4*)(tokens + b * LL);
    int4* ts = (int4*)toks;
    ts[tid] = tg[tid];
    ts[tid + 256] = tg[tid + 256];
    __syncthreads();
    if (tid < 16) qvs[tid] = toks[t0 + tid] & 255;
    __syncthreads();
    #pragma unroll
    for (int j = 0; j < 16; j++)
        lut[j][tid] = g_AT[(b * VOCAB + qvs[j]) * VOCAB + tid];

    int P = plen[b];
    float* out_lm   = out;
    float* out_gate = out + (size_t)BB * LL * VOCAB;
    float* out_attn = out_gate + (size_t)BB * LL;

    if (has_gate && tid < 16) out_gate[b * LL + t0 + tid] = g_gate[qvs[tid]];

    // log-mixed rows: 4 rows at a time, 64 threads/row, float4
    {
        int rj = tid >> 6, l64 = tid & 63;
        #pragma unroll
        for (int jb = 0; jb < 16; jb += 4) {
            int j = jb + rj;
            int qv = qvs[j];
            float4 v = ((const float4*)(g_LM + ((size_t)(b * VOCAB + qv)) * VOCAB))[l64];
            ((float4*)(out_lm + ((size_t)(b * LL + t0 + j)) * VOCAB))[l64] = v;
        }
    }
    __syncthreads();

    if (has_attn) {
        #pragma unroll
        for (int j = 0; j < 16; j++) {
            float4* orow = (float4*)(out_attn + ((size_t)(b * LL + t0 + j)) * LL);
            #pragma unroll
            for (int k2 = 0; k2 < 2; k2++) {
                int sb = (k2 * 256 + tid) * 4;
                int4 tk = *(const int4*)&toks[sb];
                float4 o;
                o.x = (sb + 0 < P) ? lut[j][tk.x & 255] : 0.f;
                o.y = (sb + 1 < P) ? lut[j][tk.y & 255] : 0.f;
                o.z = (sb + 2 < P) ? lut[j][tk.z & 255] : 0.f;
                o.w = (sb + 3 < P) ? lut[j][tk.w & 255] : 0.f;
                orow[k2 * 256 + tid] = o;
            }
        }
    }
}

// ---------------- launch ----------------
extern "C" void kernel_launch(void* const* d_in, const int* in_sizes, int n_in,
                              void* d_out, int out_size) {
    const int*   tokens = (const int*)d_in[0];
    const int*   plen   = (const int*)d_in[1];
    const float* E      = (const float*)d_in[2];
    const float* en_g   = (const float*)d_in[3];
    const float* en_b   = (const float*)d_in[4];
    const float* fn_g   = (const float*)d_in[5];
    const float* fn_b   = (const float*)d_in[6];
    const float* q_w    = (const float*)d_in[7];
    const float* q_b    = (const float*)d_in[8];
    const float* k_w    = (const float*)d_in[9];
    const float* k_b    = (const float*)d_in[10];
    const float* g_w    = (const float*)d_in[11];
    const float* g_b    = (const float*)d_in[12];

    const long long lm_sz   = (long long)BB * LL * VOCAB;
    const long long gate_sz = (long long)BB * LL;
    const long long attn_sz = (long long)BB * LL * LL;
    int has_gate = (out_size >= lm_sz + gate_sz) ? 1 : 0;
    int has_attn = (out_size >= lm_sz + gate_sz + attn_sz) ? 1 : 0;

    k_h   <<<VOCAB, 256>>>(E, en_g, en_b, fn_g, fn_b);
    k_hist<<<dim3(8, BB), 256>>>(tokens, plen);
    k_proj<<<dim3(13, 32), 256>>>(E, q_w, q_b, k_w, k_b, g_w, g_b);
    k_mix <<<VOCAB, 256>>>();
    k_write<<<dim3(LL / 16, BB), 256>>>(tokens, plen, (float*)d_out, has_gate, has_attn);
}

// round 4
// speedup vs baseline: 1.9078x; 1.0591x over previous
#include <cuda_runtime.h>
#include <cstdint>

#define VOCAB 256
#define D 512
#define A 64
#define BB 8
#define LL 2048
#define LN_EPS 1e-5f

// ---------------- scratch (device globals; no allocations) ----------------
__device__ float g_h[VOCAB * D];
__device__ float g_q[VOCAB * A];
__device__ float g_kT[A * VOCAB];          // transposed k table
__device__ float g_gate[VOCAB];
__device__ float g_logit[VOCAB * VOCAB];
__device__ float g_vprob[VOCAB * VOCAB];
__device__ float g_score[VOCAB * VOCAB];
__device__ float g_cnt[BB * VOCAB];        // final per-batch histogram (float)
__device__ float g_AT[BB * VOCAB * VOCAB];
__device__ float g_LM[BB * VOCAB * VOCAB];

// ---------------- reduction helpers ----------------
__device__ __forceinline__ float warpSum(float v) {
    #pragma unroll
    for (int o = 16; o > 0; o >>= 1) v += __shfl_xor_sync(0xFFFFFFFFu, v, o);
    return v;
}
__device__ __forceinline__ float warpMax(float v) {
    #pragma unroll
    for (int o = 16; o > 0; o >>= 1) v = fmaxf(v, __shfl_xor_sync(0xFFFFFFFFu, v, o));
    return v;
}
__device__ __forceinline__ float blockSum256(float v, float* sh) {
    int w = threadIdx.x >> 5, l = threadIdx.x & 31;
    v = warpSum(v);
    if (l == 0) sh[w] = v;
    __syncthreads();
    if (w == 0) {
        float x = (l < 8) ? sh[l] : 0.f;
        x = warpSum(x);
        if (l == 0) sh[0] = x;
    }
    __syncthreads();
    float r = sh[0];
    __syncthreads();
    return r;
}
__device__ __forceinline__ float blockMax256(float v, float* sh) {
    int w = threadIdx.x >> 5, l = threadIdx.x & 31;
    v = warpMax(v);
    if (l == 0) sh[w] = v;
    __syncthreads();
    if (w == 0) {
        float x = (l < 8) ? sh[l] : -1e30f;
        x = warpMax(x);
        if (l == 0) sh[0] = x;
    }
    __syncthreads();
    float r = sh[0];
    __syncthreads();
    return r;
}

// ---------------- k_h: h = LN(LN(embed[v])) ----------------
__global__ void k_h(const float* __restrict__ E,
                    const float* __restrict__ eg, const float* __restrict__ eb,
                    const float* __restrict__ fg, const float* __restrict__ fb) {
    int v = blockIdx.x, tid = threadIdx.x;
    __shared__ float red[8];
    float a = E[v * D + tid];
    float b = E[v * D + 256 + tid];
    float mu = blockSum256(a + b, red) * (1.f / D);
    float d0 = a - mu, d1 = b - mu;
    float var = blockSum256(d0 * d0 + d1 * d1, red) * (1.f / D);
    float inv = rsqrtf(var + LN_EPS);
    float h0 = d0 * inv * eg[tid] + eb[tid];
    float h1 = d1 * inv * eg[tid + 256] + eb[tid + 256];
    mu = blockSum256(h0 + h1, red) * (1.f / D);
    d0 = h0 - mu; d1 = h1 - mu;
    var = blockSum256(d0 * d0 + d1 * d1, red) * (1.f / D);
    inv = rsqrtf(var + LN_EPS);
    g_h[v * D + tid]       = d0 * inv * fg[tid] + fb[tid];
    g_h[v * D + 256 + tid] = d1 * inv * fg[tid + 256] + fb[tid + 256];
}

// ---------------- k_proj: logits + q + kT + gate, wide grid ---------------
__global__ void __launch_bounds__(256)
k_proj(const float* __restrict__ E,
       const float* __restrict__ qw, const float* __restrict__ qb,
       const float* __restrict__ kw, const float* __restrict__ kb,
       const float* __restrict__ gw, const float* __restrict__ gb) {
    int tid = threadIdx.x, w = tid >> 5, l = tid & 31;
    int v0 = blockIdx.y * 8;
    int obase = blockIdx.x * 32;
    __shared__ float hs[8][D];
    for (int i = tid; i < 8 * D; i += 256) ((float*)hs)[i] = g_h[v0 * D + i];
    __syncthreads();

    #pragma unroll
    for (int i = 0; i < 4; i++) {
        int o = obase + w + 8 * i;
        if (o > 384) continue;
        const float* wrow; float bias;
        if (o < 256)      { wrow = E + o * D;          bias = 0.f; }
        else if (o < 320) { wrow = qw + (o - 256) * D; bias = qb[o - 256]; }
        else if (o < 384) { wrow = kw + (o - 320) * D; bias = kb[o - 320]; }
        else              { wrow = gw;                 bias = gb[0]; }
        float e[16];
        #pragma unroll
        for (int j = 0; j < 16; j++) e[j] = wrow[l + 32 * j];
        #pragma unroll
        for (int r = 0; r < 8; r++) {
            float s = 0.f;
            #pragma unroll
            for (int j = 0; j < 16; j++) s += e[j] * hs[r][l + 32 * j];
            s = warpSum(s);
            if (l == 0) {
                int v = v0 + r;
                if (o < 256)      g_logit[v * VOCAB + o] = s;
                else if (o < 320) g_q[v * A + (o - 256)] = s + bias;
                else if (o < 384) g_kT[(o - 320) * VOCAB + v] = s + bias;
                else              g_gate[v] = 1.f / (1.f + __expf(-(s + bias)));
            }
        }
    }
}

// ---------------- k_hist: one block per batch, final counts ----------------
__global__ void __launch_bounds__(1024)
k_hist(const int* __restrict__ tokens, const int* __restrict__ plen) {
    int b = blockIdx.x, tid = threadIdx.x;
    __shared__ int c[VOCAB];
    if (tid < VOCAB) c[tid] = 0;
    __syncthreads();
    int P = plen[b];
    #pragma unroll
    for (int i = tid; i < LL; i += 1024) {
        int tk = tokens[b * LL + i];
        if (i < P && tk != 0) atomicAdd(&c[tk & 255], 1);
    }
    __syncthreads();
    if (tid < VOCAB) g_cnt[b * VOCAB + tid] = (float)c[tid];
}

// ---------------- k_sm: vocab softmax + score row per qv ------------------
__global__ void __launch_bounds__(256)
k_sm() {
    int qv = blockIdx.x, tid = threadIdx.x;
    __shared__ float red[8];
    __shared__ float qs[A];
    float lo = g_logit[qv * VOCAB + tid];
    if (tid < A) qs[tid] = g_q[qv * A + tid];
    float m = blockMax256(lo, red);
    float e = __expf(lo - m);
    float Z = blockSum256(e, red);
    g_vprob[qv * VOCAB + tid] = e * __frcp_rn(Z);
    float s = 0.f;
    #pragma unroll
    for (int d = 0; d < A; d++) s += qs[d] * g_kT[d * VOCAB + tid];
    g_score[qv * VOCAB + tid] = s * 0.125f;
}

// ---------------- k_atlm: masked softmax tables, grid (256, 8) ------------
__global__ void __launch_bounds__(256)
k_atlm() {
    int qv = blockIdx.x, b = blockIdx.y, tid = threadIdx.x;
    __shared__ float red[8];
    float sv = g_score[qv * VOCAB + tid];
    float cf = g_cnt[b * VOCAB + tid];
    float pv = g_vprob[qv * VOCAB + tid];
    float gt = g_gate[qv];
    float m = blockMax256(cf > 0.f ? sv : -1e30f, red);
    float e = __expf(sv - m);
    float Z = blockSum256(cf * e, red);
    float at = e * __frcp_rn(Z);
    if (tid == 0) at = 0.f;               // PAD column masked
    int off = (b * VOCAB + qv) * VOCAB + tid;
    g_AT[off] = at;
    float mixed = gt * pv + (1.f - gt) * (cf * at);
    g_LM[off] = __logf(fmaxf(mixed, 1e-12f));
}

// ---------------- k_write: streaming writer (HBM-bound) -------------------
__global__ void __launch_bounds__(256)
k_write(const int* __restrict__ tokens, const int* __restrict__ plen,
        float* __restrict__ out, int has_gate, int has_attn) {
    int b = blockIdx.y, t0 = blockIdx.x * 16, tid = threadIdx.x;
    __shared__ __align__(16) int toks[LL];
    __shared__ float lut[16][VOCAB];
    __shared__ int qvs[16];

    const int4* tg = (const int4*)(tokens + b * LL);
    int4* ts = (int4*)toks;
    ts[tid] = tg[tid];
    ts[tid + 256] = tg[tid + 256];
    __syncthreads();
    if (tid < 16) qvs[tid] = toks[t0 + tid] & 255;
    __syncthreads();
    #pragma unroll
    for (int j = 0; j < 16; j++)
        lut[j][tid] = g_AT[(b * VOCAB + qvs[j]) * VOCAB + tid];

    int P = plen[b];
    float* out_lm   = out;
    float* out_gate = out + (size_t)BB * LL * VOCAB;
    float* out_attn = out_gate + (size_t)BB * LL;

    if (has_gate && tid < 16) out_gate[b * LL + t0 + tid] = g_gate[qvs[tid]];

    // log-mixed rows: 4 rows at a time, 64 threads/row, float4
    {
        int rj = tid >> 6, l64 = tid & 63;
        #pragma unroll
        for (int jb = 0; jb < 16; jb += 4) {
            int j = jb + rj;
            int qv = qvs[j];
            float4 v = ((const float4*)(g_LM + ((size_t)(b * VOCAB + qv)) * VOCAB))[l64];
            ((float4*)(out_lm + ((size_t)(b * LL + t0 + j)) * VOCAB))[l64] = v;
        }
    }
    __syncthreads();

    if (has_attn) {
        #pragma unroll
        for (int j = 0; j < 16; j++) {
            float4* orow = (float4*)(out_attn + ((size_t)(b * LL + t0 + j)) * LL);
            #pragma unroll
            for (int k2 = 0; k2 < 2; k2++) {
                int sb = (k2 * 256 + tid) * 4;
                int4 tk = *(const int4*)&toks[sb];
                float4 o;
                o.x = (sb + 0 < P) ? lut[j][tk.x & 255] : 0.f;
                o.y = (sb + 1 < P) ? lut[j][tk.y & 255] : 0.f;
                o.z = (sb + 2 < P) ? lut[j][tk.z & 255] : 0.f;
                o.w = (sb + 3 < P) ? lut[j][tk.w & 255] : 0.f;
                orow[k2 * 256 + tid] = o;
            }
        }
    }
}

// ---------------- launch ----------------
extern "C" void kernel_launch(void* const* d_in, const int* in_sizes, int n_in,
                              void* d_out, int out_size) {
    const int*   tokens = (const int*)d_in[0];
    const int*   plen   = (const int*)d_in[1];
    const float* E      = (const float*)d_in[2];
    const float* en_g   = (const float*)d_in[3];
    const float* en_b   = (const float*)d_in[4];
    const float* fn_g   = (const float*)d_in[5];
    const float* fn_b   = (const float*)d_in[6];
    const float* q_w    = (const float*)d_in[7];
    const float* q_b    = (const float*)d_in[8];
    const float* k_w    = (const float*)d_in[9];
    const float* k_b    = (const float*)d_in[10];
    const float* g_w    = (const float*)d_in[11];
    const float* g_b    = (const float*)d_in[12];

    const long long lm_sz   = (long long)BB * LL * VOCAB;
    const long long gate_sz = (long long)BB * LL;
    const long long attn_sz = (long long)BB * LL * LL;
    int has_gate = (out_size >= lm_sz + gate_sz) ? 1 : 0;
    int has_attn = (out_size >= lm_sz + gate_sz + attn_sz) ? 1 : 0;

    k_h    <<<VOCAB, 256>>>(E, en_g, en_b, fn_g, fn_b);
    k_hist <<<BB, 1024>>>(tokens, plen);
    k_proj <<<dim3(13, 32), 256>>>(E, q_w, q_b, k_w, k_b, g_w, g_b);
    k_sm   <<<VOCAB, 256>>>();
    k_atlm <<<dim3(VOCAB, BB), 256>>>();
    k_write<<<dim3(LL / 16, BB), 256>>>(tokens, plen, (float*)d_out, has_gate, has_attn);
}

// round 5
// speedup vs baseline: 2.3027x; 1.2070x over previous
#include <cuda_runtime.h>
#include <cstdint>

#define VOCAB 256
#define D 512
#define A 64
#define BB 8
#define LL 2048
#define LN_EPS 1e-5f

// ---------------- scratch (device globals; no allocations) ----------------
__device__ float g_q[VOCAB * A];
__device__ float g_kT[A * VOCAB];          // transposed k table
__device__ float g_gate[VOCAB];
__device__ float g_logit[VOCAB * VOCAB];
__device__ float g_cnt[BB * VOCAB];        // per-batch histogram (float)
__device__ float g_AT[BB * VOCAB * VOCAB];
__device__ float g_LM[BB * VOCAB * VOCAB];

// ---------------- reduction helpers ----------------
__device__ __forceinline__ float warpSum(float v) {
    #pragma unroll
    for (int o = 16; o > 0; o >>= 1) v += __shfl_xor_sync(0xFFFFFFFFu, v, o);
    return v;
}
__device__ __forceinline__ float warpMax(float v) {
    #pragma unroll
    for (int o = 16; o > 0; o >>= 1) v = fmaxf(v, __shfl_xor_sync(0xFFFFFFFFu, v, o));
    return v;
}
__device__ __forceinline__ float blockSum256(float v, float* sh) {
    int w = threadIdx.x >> 5, l = threadIdx.x & 31;
    v = warpSum(v);
    if (l == 0) sh[w] = v;
    __syncthreads();
    if (w == 0) {
        float x = (l < 8) ? sh[l] : 0.f;
        x = warpSum(x);
        if (l == 0) sh[0] = x;
    }
    __syncthreads();
    float r = sh[0];
    __syncthreads();
    return r;
}
__device__ __forceinline__ float blockMax256(float v, float* sh) {
    int w = threadIdx.x >> 5, l = threadIdx.x & 31;
    v = warpMax(v);
    if (l == 0) sh[w] = v;
    __syncthreads();
    if (w == 0) {
        float x = (l < 8) ? sh[l] : -1e30f;
        x = warpMax(x);
        if (l == 0) sh[0] = x;
    }
    __syncthreads();
    float r = sh[0];
    __syncthreads();
    return r;
}

// ---------------- k_tabs: histogram blocks + (h -> proj) blocks -----------
// blocks [0,8):     per-batch prefix histogram
// blocks [8,424):   proj block pb: v-rows (pb%32)*8.. , o-cols (pb/32)*32..
// output column o: [0,256) logits, [256,320) q, [320,384) kT, 384 gate
__global__ void __launch_bounds__(256)
k_tabs(const int* __restrict__ tokens, const int* __restrict__ plen,
       const float* __restrict__ E,
       const float* __restrict__ eg, const float* __restrict__ eb,
       const float* __restrict__ fg, const float* __restrict__ fb,
       const float* __restrict__ qw, const float* __restrict__ qb,
       const float* __restrict__ kw, const float* __restrict__ kb,
       const float* __restrict__ gw, const float* __restrict__ gb) {
    int tid = threadIdx.x, w = tid >> 5, l = tid & 31;

    if (blockIdx.x < 8) {
        // ---- histogram for batch b ----
        int b = blockIdx.x;
        __shared__ int c[VOCAB];
        c[tid] = 0;
        __syncthreads();
        int P = plen[b];
        #pragma unroll
        for (int it = 0; it < 8; it++) {
            int i = it * 256 + tid;
            int tk = tokens[b * LL + i];
            if (i < P && tk != 0) atomicAdd(&c[tk & 255], 1);
        }
        __syncthreads();
        g_cnt[b * VOCAB + tid] = (float)c[tid];
        return;
    }

    int pb = blockIdx.x - 8;
    int v0 = (pb & 31) * 8;
    int obase = (pb >> 5) * 32;
    __shared__ float hs[8][D];

    // ---- warp w computes h row v0+w via two LayerNorms (shuffles only) ----
    {
        int v = v0 + w;
        float e[16];
        #pragma unroll
        for (int j = 0; j < 16; j++) e[j] = E[v * D + l + 32 * j];
        float s = 0.f;
        #pragma unroll
        for (int j = 0; j < 16; j++) s += e[j];
        float mu = warpSum(s) * (1.f / D);
        float vv = 0.f;
        #pragma unroll
        for (int j = 0; j < 16; j++) { e[j] -= mu; vv += e[j] * e[j]; }
        float inv = rsqrtf(warpSum(vv) * (1.f / D) + LN_EPS);
        #pragma unroll
        for (int j = 0; j < 16; j++)
            e[j] = e[j] * inv * eg[l + 32 * j] + eb[l + 32 * j];
        s = 0.f;
        #pragma unroll
        for (int j = 0; j < 16; j++) s += e[j];
        mu = warpSum(s) * (1.f / D);
        vv = 0.f;
        #pragma unroll
        for (int j = 0; j < 16; j++) { e[j] -= mu; vv += e[j] * e[j]; }
        inv = rsqrtf(warpSum(vv) * (1.f / D) + LN_EPS);
        #pragma unroll
        for (int j = 0; j < 16; j++)
            hs[w][l + 32 * j] = e[j] * inv * fg[l + 32 * j] + fb[l + 32 * j];
    }
    __syncthreads();

    // ---- projections ----
    #pragma unroll
    for (int i = 0; i < 4; i++) {
        int o = obase + w + 8 * i;
        if (o > 384) continue;
        const float* wrow; float bias;
        if (o < 256)      { wrow = E + o * D;          bias = 0.f; }
        else if (o < 320) { wrow = qw + (o - 256) * D; bias = qb[o - 256]; }
        else if (o < 384) { wrow = kw + (o - 320) * D; bias = kb[o - 320]; }
        else              { wrow = gw;                 bias = gb[0]; }
        float e[16];
        #pragma unroll
        for (int j = 0; j < 16; j++) e[j] = wrow[l + 32 * j];
        #pragma unroll
        for (int r = 0; r < 8; r++) {
            float s = 0.f;
            #pragma unroll
            for (int j = 0; j < 16; j++) s += e[j] * hs[r][l + 32 * j];
            s = warpSum(s);
            if (l == 0) {
                int v = v0 + r;
                if (o < 256)      g_logit[v * VOCAB + o] = s;
                else if (o < 320) g_q[v * A + (o - 256)] = s + bias;
                else if (o < 384) g_kT[(o - 320) * VOCAB + v] = s + bias;
                else              g_gate[v] = 1.f / (1.f + __expf(-(s + bias)));
            }
        }
    }
}

// ---------------- k_mix2: softmax + scores + AT/LM (one block per qv) -----
__global__ void __launch_bounds__(256)
k_mix2() {
    int qv = blockIdx.x, tid = threadIdx.x, w = tid >> 5, l = tid & 31;
    __shared__ float red[8];
    __shared__ float sc[VOCAB];
    __shared__ float sp[VOCAB];
    __shared__ float qs[A];

    float lo = g_logit[qv * VOCAB + tid];
    if (tid < A) qs[tid] = g_q[qv * A + tid];
    float m = blockMax256(lo, red);
    float e = __expf(lo - m);
    float Z = blockSum256(e, red);
    sp[tid] = e * __frcp_rn(Z);

    // scores: thread-per-kv (dense, coalesced kT reads)
    float s = 0.f;
    #pragma unroll
    for (int d = 0; d < A; d++) s += qs[d] * g_kT[d * VOCAB + tid];
    sc[tid] = s * 0.125f;
    __syncthreads();

    // warp w owns batch w: shuffles only
    {
        int b = w;
        float gt = g_gate[qv];
        float sv[8], cf[8], pv[8];
        float mx = -1e30f;
        #pragma unroll
        for (int j = 0; j < 8; j++) {
            int v = l + 32 * j;
            sv[j] = sc[v];
            cf[j] = g_cnt[b * VOCAB + v];
            pv[j] = sp[v];
            mx = fmaxf(mx, cf[j] > 0.f ? sv[j] : -1e30f);
        }
        mx = warpMax(mx);
        float ex[8], z = 0.f;
        #pragma unroll
        for (int j = 0; j < 8; j++) {
            ex[j] = __expf(sv[j] - mx);
            z += cf[j] * ex[j];
        }
        z = warpSum(z);
        float invz = __frcp_rn(z);
        size_t base = ((size_t)b * VOCAB + qv) * VOCAB;
        #pragma unroll
        for (int j = 0; j < 8; j++) {
            int v = l + 32 * j;
            float at = ex[j] * invz;
            if (v == 0) at = 0.f;     // PAD column masked
            g_AT[base + v] = at;
            float mixed = gt * pv[j] + (1.f - gt) * (cf[j] * at);
            g_LM[base + v] = __logf(fmaxf(mixed, 1e-12f));
        }
    }
}

// ---------------- k_write: streaming writer (HBM-bound) -------------------
__global__ void __launch_bounds__(256)
k_write(const int* __restrict__ tokens, const int* __restrict__ plen,
        float* __restrict__ out, int has_gate, int has_attn) {
    int b = blockIdx.y, t0 = blockIdx.x * 16, tid = threadIdx.x;
    __shared__ __align__(16) int toks[LL];
    __shared__ float lut[16][VOCAB];
    __shared__ int qvs[16];

    const int4* tg = (const int4*)(tokens + b * LL);
    int4* ts = (int4*)toks;
    ts[tid] = tg[tid];
    ts[tid + 256] = tg[tid + 256];
    __syncthreads();
    if (tid < 16) qvs[tid] = toks[t0 + tid] & 255;
    __syncthreads();
    #pragma unroll
    for (int j = 0; j < 16; j++)
        lut[j][tid] = g_AT[(b * VOCAB + qvs[j]) * VOCAB + tid];

    int P = plen[b];
    float* out_lm   = out;
    float* out_gate = out + (size_t)BB * LL * VOCAB;
    float* out_attn = out_gate + (size_t)BB * LL;

    if (has_gate && tid < 16) out_gate[b * LL + t0 + tid] = g_gate[qvs[tid]];

    // log-mixed rows: 4 rows at a time, 64 threads/row, float4 streaming
    {
        int rj = tid >> 6, l64 = tid & 63;
        #pragma unroll
        for (int jb = 0; jb < 16; jb += 4) {
            int j = jb + rj;
            int qv = qvs[j];
            float4 v = ((const float4*)(g_LM + ((size_t)(b * VOCAB + qv)) * VOCAB))[l64];
            __stcs((float4*)(out_lm + ((size_t)(b * LL + t0 + j)) * VOCAB) + l64, v);
        }
    }
    __syncthreads();

    if (has_attn) {
        #pragma unroll
        for (int j = 0; j < 16; j++) {
            float4* orow = (float4*)(out_attn + ((size_t)(b * LL + t0 + j)) * LL);
            #pragma unroll
            for (int k2 = 0; k2 < 2; k2++) {
                int sb = (k2 * 256 + tid) * 4;
                int4 tk = *(const int4*)&toks[sb];
                float4 o;
                o.x = (sb + 0 < P) ? lut[j][tk.x & 255] : 0.f;
                o.y = (sb + 1 < P) ? lut[j][tk.y & 255] : 0.f;
                o.z = (sb + 2 < P) ? lut[j][tk.z & 255] : 0.f;
                o.w = (sb + 3 < P) ? lut[j][tk.w & 255] : 0.f;
                __stcs(orow + k2 * 256 + tid, o);
            }
        }
    }
}

// ---------------- launch ----------------
extern "C" void kernel_launch(void* const* d_in, const int* in_sizes, int n_in,
                              void* d_out, int out_size) {
    const int*   tokens = (const int*)d_in[0];
    const int*   plen   = (const int*)d_in[1];
    const float* E      = (const float*)d_in[2];
    const float* en_g   = (const float*)d_in[3];
    const float* en_b   = (const float*)d_in[4];
    const float* fn_g   = (const float*)d_in[5];
    const float* fn_b   = (const float*)d_in[6];
    const float* q_w    = (const float*)d_in[7];
    const float* q_b    = (const float*)d_in[8];
    const float* k_w    = (const float*)d_in[9];
    const float* k_b    = (const float*)d_in[10];
    const float* g_w    = (const float*)d_in[11];
    const float* g_b    = (const float*)d_in[12];

    const long long lm_sz   = (long long)BB * LL * VOCAB;
    const long long gate_sz = (long long)BB * LL;
    const long long attn_sz = (long long)BB * LL * LL;
    int has_gate = (out_size >= lm_sz + gate_sz) ? 1 : 0;
    int has_attn = (out_size >= lm_sz + gate_sz + attn_sz) ? 1 : 0;

    k_tabs <<<8 + 416, 256>>>(tokens, plen, E, en_g, en_b, fn_g, fn_b,
                              q_w, q_b, k_w, k_b, g_w, g_b);
    k_mix2 <<<VOCAB, 256>>>();
    k_write<<<dim3(LL / 16, BB), 256>>>(tokens, plen, (float*)d_out, has_gate, has_attn);
}

// round 7
// speedup vs baseline: 2.4783x; 1.0762x over previous
#include <cuda_runtime.h>
#include <cstdint>

#define VOCAB 256
#define D 512
#define A 64
#define BB 8
#define LL 2048
#define LN_EPS 1e-5f

// ---------------- scratch (device globals; no allocations) ----------------
__device__ float g_q[VOCAB * A];
__device__ float g_kT[A * VOCAB];          // transposed k table
__device__ float g_gate[VOCAB];
__device__ float g_logit[VOCAB * VOCAB];
__device__ float g_vprob[VOCAB * VOCAB];
__device__ float g_score[VOCAB * VOCAB];
__device__ float g_cnt[BB * VOCAB];        // per-batch histogram (float)

// ---------------- reduction helpers ----------------
__device__ __forceinline__ float warpSum(float v) {
    #pragma unroll
    for (int o = 16; o > 0; o >>= 1) v += __shfl_xor_sync(0xFFFFFFFFu, v, o);
    return v;
}
__device__ __forceinline__ float warpMax(float v) {
    #pragma unroll
    for (int o = 16; o > 0; o >>= 1) v = fmaxf(v, __shfl_xor_sync(0xFFFFFFFFu, v, o));
    return v;
}
__device__ __forceinline__ float blockSum256(float v, float* sh) {
    int w = threadIdx.x >> 5, l = threadIdx.x & 31;
    v = warpSum(v);
    if (l == 0) sh[w] = v;
    __syncthreads();
    if (w == 0) {
        float x = (l < 8) ? sh[l] : 0.f;
        x = warpSum(x);
        if (l == 0) sh[0] = x;
    }
    __syncthreads();
    float r = sh[0];
    __syncthreads();
    return r;
}
__device__ __forceinline__ float blockMax256(float v, float* sh) {
    int w = threadIdx.x >> 5, l = threadIdx.x & 31;
    v = warpMax(v);
    if (l == 0) sh[w] = v;
    __syncthreads();
    if (w == 0) {
        float x = (l < 8) ? sh[l] : -1e30f;
        x = warpMax(x);
        if (l == 0) sh[0] = x;
    }
    __syncthreads();
    float r = sh[0];
    __syncthreads();
    return r;
}

// ---------------- k_tabs: histogram blocks + (h -> proj) blocks -----------
// blocks [0,8):     per-batch prefix histogram
// blocks [8,424):   proj block pb: v-rows (pb%32)*8.. , o-cols (pb/32)*32..
// output column o: [0,256) logits, [256,320) q, [320,384) kT, 384 gate
__global__ void __launch_bounds__(256)
k_tabs(const int* __restrict__ tokens, const int* __restrict__ plen,
       const float* __restrict__ E,
       const float* __restrict__ eg, const float* __restrict__ eb,
       const float* __restrict__ fg, const float* __restrict__ fb,
       const float* __restrict__ qw, const float* __restrict__ qb,
       const float* __restrict__ kw, const float* __restrict__ kb,
       const float* __restrict__ gw, const float* __restrict__ gb) {
    int tid = threadIdx.x, w = tid >> 5, l = tid & 31;

    if (blockIdx.x < 8) {
        int b = blockIdx.x;
        __shared__ int c[VOCAB];
        c[tid] = 0;
        __syncthreads();
        int P = plen[b];
        #pragma unroll
        for (int it = 0; it < 8; it++) {
            int i = it * 256 + tid;
            int tk = tokens[b * LL + i];
            if (i < P && tk != 0) atomicAdd(&c[tk & 255], 1);
        }
        __syncthreads();
        g_cnt[b * VOCAB + tid] = (float)c[tid];
        return;
    }

    int pb = blockIdx.x - 8;
    int v0 = (pb & 31) * 8;
    int obase = (pb >> 5) * 32;
    __shared__ __align__(16) float hs[8][D];

    // ---- warp w computes h row v0+w via two LayerNorms (shuffles only) ----
    {
        int v = v0 + w;
        float e[16];
        #pragma unroll
        for (int j = 0; j < 16; j++) e[j] = E[v * D + l + 32 * j];
        float s = 0.f;
        #pragma unroll
        for (int j = 0; j < 16; j++) s += e[j];
        float mu = warpSum(s) * (1.f / D);
        float vv = 0.f;
        #pragma unroll
        for (int j = 0; j < 16; j++) { e[j] -= mu; vv += e[j] * e[j]; }
        float inv = rsqrtf(warpSum(vv) * (1.f / D) + LN_EPS);
        #pragma unroll
        for (int j = 0; j < 16; j++)
            e[j] = e[j] * inv * eg[l + 32 * j] + eb[l + 32 * j];
        s = 0.f;
        #pragma unroll
        for (int j = 0; j < 16; j++) s += e[j];
        mu = warpSum(s) * (1.f / D);
        vv = 0.f;
        #pragma unroll
        for (int j = 0; j < 16; j++) { e[j] -= mu; vv += e[j] * e[j]; }
        inv = rsqrtf(warpSum(vv) * (1.f / D) + LN_EPS);
        #pragma unroll
        for (int j = 0; j < 16; j++)
            hs[w][l + 32 * j] = e[j] * inv * fg[l + 32 * j] + fb[l + 32 * j];
    }
    __syncthreads();

    // ---- projections: warp handles 4 o's simultaneously (register-blocked)
    int olist[4];
    bool oval[4];
    const float4* wrow4[4];
    float bias[4];
    #pragma unroll
    for (int oi = 0; oi < 4; oi++) {
        int o = obase + w + 8 * oi;
        oval[oi] = (o <= 384);
        int oe = oval[oi] ? o : 384;
        olist[oi] = oe;
        const float* wr;
        if (oe < 256)      { wr = E + oe * D;          bias[oi] = 0.f; }
        else if (oe < 320) { wr = qw + (oe - 256) * D; bias[oi] = qb[oe - 256]; }
        else if (oe < 384) { wr = kw + (oe - 320) * D; bias[oi] = kb[oe - 320]; }
        else               { wr = gw;                  bias[oi] = gb[0]; }
        wrow4[oi] = (const float4*)wr;
    }

    float4 e4[4][4];
    #pragma unroll
    for (int oi = 0; oi < 4; oi++)
        #pragma unroll
        for (int jj = 0; jj < 4; jj++)
            e4[oi][jj] = wrow4[oi][l + 32 * jj];

    float acc[8][4];
    #pragma unroll
    for (int r = 0; r < 8; r++)
        #pragma unroll
        for (int oi = 0; oi < 4; oi++) acc[r][oi] = 0.f;

    const float4* hs4 = (const float4*)hs;   // [8 * 128]
    #pragma unroll
    for (int r = 0; r < 8; r++) {
        #pragma unroll
        for (int jj = 0; jj < 4; jj++) {
            float4 h4 = hs4[r * 128 + l + 32 * jj];
            #pragma unroll
            for (int oi = 0; oi < 4; oi++) {
                acc[r][oi] += e4[oi][jj].x * h4.x + e4[oi][jj].y * h4.y
                            + e4[oi][jj].z * h4.z + e4[oi][jj].w * h4.w;
            }
        }
    }

    #pragma unroll
    for (int oi = 0; oi < 4; oi++) {
        #pragma unroll
        for (int r = 0; r < 8; r++) {
            float s = warpSum(acc[r][oi]);
            if (l == 0 && oval[oi]) {
                int o = olist[oi];
                int v = v0 + r;
                if (o < 256)      g_logit[v * VOCAB + o] = s;
                else if (o < 320) g_q[v * A + (o - 256)] = s + bias[oi];
                else if (o < 384) g_kT[(o - 320) * VOCAB + v] = s + bias[oi];
                else              g_gate[v] = 1.f / (1.f + __expf(-(s + bias[oi])));
            }
        }
    }
}

// ---------------- k_sm: vocab softmax + score row per qv ------------------
__global__ void __launch_bounds__(256)
k_sm() {
    int qv = blockIdx.x, tid = threadIdx.x;
    __shared__ float red[8];
    __shared__ float qs[A];
    float lo = g_logit[qv * VOCAB + tid];
    if (tid < A) qs[tid] = g_q[qv * A + tid];
    __syncthreads();                 // qs visible to ALL warps before reading
    float s = 0.f;
    #pragma unroll
    for (int d = 0; d < A; d++) s += qs[d] * g_kT[d * VOCAB + tid];
    g_score[qv * VOCAB + tid] = s * 0.125f;
    float m = blockMax256(lo, red);
    float e = __expf(lo - m);
    float Z = blockSum256(e, red);
    g_vprob[qv * VOCAB + tid] = e * __frcp_rn(Z);
}

// ---------------- k_write: AT/LM compute + streaming writer ---------------
__global__ void __launch_bounds__(256)
k_write(const int* __restrict__ tokens, const int* __restrict__ plen,
        float* __restrict__ out, int has_gate, int has_attn) {
    int b = blockIdx.y, t0 = blockIdx.x * 16, tid = threadIdx.x;
    int w = tid >> 5, l = tid & 31;
    __shared__ __align__(16) int toks[LL];
    __shared__ float lut[16][VOCAB];
    __shared__ float scnt[VOCAB];
    __shared__ int qvs[16];

    scnt[tid] = g_cnt[b * VOCAB + tid];
    const int4* tg = (const int4*)(tokens + b * LL);
    int4* ts = (int4*)toks;
    ts[tid] = tg[tid];
    ts[tid + 256] = tg[tid + 256];
    __syncthreads();
    if (tid < 16) qvs[tid] = toks[t0 + tid] & 255;
    __syncthreads();

    // ---- AT rows: warp w computes rows w and w+8 (shuffles only) ----
    #pragma unroll
    for (int jj = 0; jj < 2; jj++) {
        int j = w + jj * 8;
        int qv = qvs[j];
        float sv[8], cf[8];
        float mx = -1e30f;
        #pragma unroll
        for (int m = 0; m < 8; m++) {
            int v = l + 32 * m;
            sv[m] = g_score[qv * VOCAB + v];
            cf[m] = scnt[v];
            mx = fmaxf(mx, cf[m] > 0.f ? sv[m] : -1e30f);
        }
        mx = warpMax(mx);
        float ex[8], z = 0.f;
        #pragma unroll
        for (int m = 0; m < 8; m++) {
            ex[m] = __expf(sv[m] - mx);
            z += cf[m] * ex[m];
        }
        z = warpSum(z);
        float invz = __frcp_rn(z);
        #pragma unroll
        for (int m = 0; m < 8; m++) {
            int v = l + 32 * m;
            float at = ex[m] * invz;
            if (v == 0) at = 0.f;            // PAD column masked
            lut[j][v] = at;
        }
    }
    __syncthreads();

    int P = plen[b];
    float* out_lm   = out;
    float* out_gate = out + (size_t)BB * LL * VOCAB;
    float* out_attn = out_gate + (size_t)BB * LL;

    if (has_gate && tid < 16) out_gate[b * LL + t0 + tid] = g_gate[qvs[tid]];

    // ---- LM: thread = column, 16 rows ----
    float cn = scnt[tid];
    #pragma unroll
    for (int j = 0; j < 16; j++) {
        int qv = qvs[j];
        float gt = g_gate[qv];
        float pv = g_vprob[qv * VOCAB + tid];
        float mixed = gt * pv + (1.f - gt) * (cn * lut[j][tid]);
        __stcs(out_lm + ((size_t)(b * LL + t0 + j)) * VOCAB + tid,
               __logf(fmaxf(mixed, 1e-12f)));
    }

    // ---- attn streaming ----
    if (has_attn) {
        #pragma unroll
        for (int j = 0; j < 16; j++) {
            float4* orow = (float4*)(out_attn + ((size_t)(b * LL + t0 + j)) * LL);
            #pragma unroll
            for (int k2 = 0; k2 < 2; k2++) {
                int sb = (k2 * 256 + tid) * 4;
                int4 tk = *(const int4*)&toks[sb];
                float4 o;
                o.x = (sb + 0 < P) ? lut[j][tk.x & 255] : 0.f;
                o.y = (sb + 1 < P) ? lut[j][tk.y & 255] : 0.f;
                o.z = (sb + 2 < P) ? lut[j][tk.z & 255] : 0.f;
                o.w = (sb + 3 < P) ? lut[j][tk.w & 255] : 0.f;
                __stcs(orow + k2 * 256 + tid, o);
            }
        }
    }
}

// ---------------- launch ----------------
extern "C" void kernel_launch(void* const* d_in, const int* in_sizes, int n_in,
                              void* d_out, int out_size) {
    const int*   tokens = (const int*)d_in[0];
    const int*   plen   = (const int*)d_in[1];
    const float* E      = (const float*)d_in[2];
    const float* en_g   = (const float*)d_in[3];
    const float* en_b   = (const float*)d_in[4];
    const float* fn_g   = (const float*)d_in[5];
    const float* fn_b   = (const float*)d_in[6];
    const float* q_w    = (const float*)d_in[7];
    const float* q_b    = (const float*)d_in[8];
    const float* k_w    = (const float*)d_in[9];
    const float* k_b    = (const float*)d_in[10];
    const float* g_w    = (const float*)d_in[11];
    const float* g_b    = (const float*)d_in[12];

    const long long lm_sz   = (long long)BB * LL * VOCAB;
    const long long gate_sz = (long long)BB * LL;
    const long long attn_sz = (long long)BB * LL * LL;
    int has_gate = (out_size >= lm_sz + gate_sz) ? 1 : 0;
    int has_attn = (out_size >= lm_sz + gate_sz + attn_sz) ? 1 : 0;

    k_tabs <<<8 + 416, 256>>>(tokens, plen, E, en_g, en_b, fn_g, fn_b,
                              q_w, q_b, k_w, k_b, g_w, g_b);
    k_sm   <<<VOCAB, 256>>>();
    k_write<<<dim3(LL / 16, BB), 256>>>(tokens, plen, (float*)d_out, has_gate, has_attn);
}

// round 8
// speedup vs baseline: 2.5622x; 1.0339x over previous
#include <cuda_runtime.h>
#include <cstdint>

#define VOCAB 256
#define D 512
#define A 64
#define BB 8
#define LL 2048
#define LN_EPS 1e-5f

// ---------------- scratch (device globals; no allocations) ----------------
__device__ float g_q[VOCAB * A];
__device__ float g_kT[A * VOCAB];          // transposed k table
__device__ float g_gate[VOCAB];
__device__ float g_logit[VOCAB * VOCAB];
__device__ float g_vprob[VOCAB * VOCAB];
__device__ float g_score[VOCAB * VOCAB];
__device__ float g_cnt[BB * VOCAB];        // per-batch histogram (float)

// ---------------- reduction helpers ----------------
__device__ __forceinline__ float warpSum(float v) {
    #pragma unroll
    for (int o = 16; o > 0; o >>= 1) v += __shfl_xor_sync(0xFFFFFFFFu, v, o);
    return v;
}
__device__ __forceinline__ float warpMax(float v) {
    #pragma unroll
    for (int o = 16; o > 0; o >>= 1) v = fmaxf(v, __shfl_xor_sync(0xFFFFFFFFu, v, o));
    return v;
}
__device__ __forceinline__ float blockSum256(float v, float* sh) {
    int w = threadIdx.x >> 5, l = threadIdx.x & 31;
    v = warpSum(v);
    if (l == 0) sh[w] = v;
    __syncthreads();
    if (w == 0) {
        float x = (l < 8) ? sh[l] : 0.f;
        x = warpSum(x);
        if (l == 0) sh[0] = x;
    }
    __syncthreads();
    float r = sh[0];
    __syncthreads();
    return r;
}
__device__ __forceinline__ float blockMax256(float v, float* sh) {
    int w = threadIdx.x >> 5, l = threadIdx.x & 31;
    v = warpMax(v);
    if (l == 0) sh[w] = v;
    __syncthreads();
    if (w == 0) {
        float x = (l < 8) ? sh[l] : -1e30f;
        x = warpMax(x);
        if (l == 0) sh[0] = x;
    }
    __syncthreads();
    float r = sh[0];
    __syncthreads();
    return r;
}

// ---------------- k_tabs: histogram blocks + (h -> proj) blocks -----------
// blocks [0,8):   per-batch prefix histogram
// blocks [8,808): proj block pb: v-rows (pb%32)*8.. , o-cols (pb/32)*16..
// output column o: [0,256) logits, [256,320) q, [320,384) kT, 384 gate
__global__ void __launch_bounds__(256)
k_tabs(const int* __restrict__ tokens, const int* __restrict__ plen,
       const float* __restrict__ E,
       const float* __restrict__ eg, const float* __restrict__ eb,
       const float* __restrict__ fg, const float* __restrict__ fb,
       const float* __restrict__ qw, const float* __restrict__ qb,
       const float* __restrict__ kw, const float* __restrict__ kb,
       const float* __restrict__ gw, const float* __restrict__ gb) {
    int tid = threadIdx.x, w = tid >> 5, l = tid & 31;

    if (blockIdx.x < 8) {
        int b = blockIdx.x;
        __shared__ int c[VOCAB];
        c[tid] = 0;
        __syncthreads();
        int P = plen[b];
        #pragma unroll
        for (int it = 0; it < 8; it++) {
            int i = it * 256 + tid;
            int tk = tokens[b * LL + i];
            if (i < P && tk != 0) atomicAdd(&c[tk & 255], 1);
        }
        __syncthreads();
        g_cnt[b * VOCAB + tid] = (float)c[tid];
        return;
    }

    int pb = blockIdx.x - 8;
    int v0 = (pb & 31) * 8;
    int obase = (pb >> 5) * 16;              // 25 col-groups of 16
    __shared__ __align__(16) float4 hs4[8 * 128];

    // ---- per-warp setup: 2 output columns ----
    int olist[2];
    bool oval[2];
    float bias[2];
    const float4* wrow4[2];
    #pragma unroll
    for (int oi = 0; oi < 2; oi++) {
        int o = obase + w * 2 + oi;
        oval[oi] = (o <= 384);
        int oe = oval[oi] ? o : 384;
        olist[oi] = oe;
        const float* wr;
        if (oe < 256)      { wr = E + oe * D;          bias[oi] = 0.f; }
        else if (oe < 320) { wr = qw + (oe - 256) * D; bias[oi] = qb[oe - 256]; }
        else if (oe < 384) { wr = kw + (oe - 320) * D; bias[oi] = kb[oe - 320]; }
        else               { wr = gw;                  bias[oi] = gb[0]; }
        wrow4[oi] = (const float4*)wr;
    }

    // issue weight loads FIRST (independent of LN) so L2 latency overlaps
    float4 e4[2][4];
    #pragma unroll
    for (int oi = 0; oi < 2; oi++)
        #pragma unroll
        for (int jj = 0; jj < 4; jj++)
            e4[oi][jj] = wrow4[oi][l + 32 * jj];

    // ---- warp w computes h row v0+w via two LayerNorms (float4 + shuffles)
    {
        int v = v0 + w;
        const float4* E4 = (const float4*)E;
        float4 ef[4];
        #pragma unroll
        for (int j = 0; j < 4; j++) ef[j] = E4[v * 128 + l + 32 * j];
        float s = 0.f;
        #pragma unroll
        for (int j = 0; j < 4; j++) s += ef[j].x + ef[j].y + ef[j].z + ef[j].w;
        float mu = warpSum(s) * (1.f / D);
        float vv = 0.f;
        #pragma unroll
        for (int j = 0; j < 4; j++) {
            ef[j].x -= mu; ef[j].y -= mu; ef[j].z -= mu; ef[j].w -= mu;
            vv += ef[j].x * ef[j].x + ef[j].y * ef[j].y
                + ef[j].z * ef[j].z + ef[j].w * ef[j].w;
        }
        float inv = rsqrtf(warpSum(vv) * (1.f / D) + LN_EPS);
        {
            const float4* G = (const float4*)eg;
            const float4* Bv = (const float4*)eb;
            #pragma unroll
            for (int j = 0; j < 4; j++) {
                float4 g4 = G[l + 32 * j], b4 = Bv[l + 32 * j];
                ef[j].x = ef[j].x * inv * g4.x + b4.x;
                ef[j].y = ef[j].y * inv * g4.y + b4.y;
                ef[j].z = ef[j].z * inv * g4.z + b4.z;
                ef[j].w = ef[j].w * inv * g4.w + b4.w;
            }
        }
        s = 0.f;
        #pragma unroll
        for (int j = 0; j < 4; j++) s += ef[j].x + ef[j].y + ef[j].z + ef[j].w;
        mu = warpSum(s) * (1.f / D);
        vv = 0.f;
        #pragma unroll
        for (int j = 0; j < 4; j++) {
            ef[j].x -= mu; ef[j].y -= mu; ef[j].z -= mu; ef[j].w -= mu;
            vv += ef[j].x * ef[j].x + ef[j].y * ef[j].y
                + ef[j].z * ef[j].z + ef[j].w * ef[j].w;
        }
        inv = rsqrtf(warpSum(vv) * (1.f / D) + LN_EPS);
        {
            const float4* G = (const float4*)fg;
            const float4* Bv = (const float4*)fb;
            #pragma unroll
            for (int j = 0; j < 4; j++) {
                float4 g4 = G[l + 32 * j], b4 = Bv[l + 32 * j];
                float4 hv;
                hv.x = ef[j].x * inv * g4.x + b4.x;
                hv.y = ef[j].y * inv * g4.y + b4.y;
                hv.z = ef[j].z * inv * g4.z + b4.z;
                hv.w = ef[j].w * inv * g4.w + b4.w;
                hs4[w * 128 + l + 32 * j] = hv;
            }
        }
    }
    __syncthreads();

    // ---- projections: 8 v-rows x 2 o's, register-blocked ----
    float acc[8][2];
    #pragma unroll
    for (int r = 0; r < 8; r++) { acc[r][0] = 0.f; acc[r][1] = 0.f; }

    #pragma unroll
    for (int r = 0; r < 8; r++) {
        #pragma unroll
        for (int jj = 0; jj < 4; jj++) {
            float4 h4 = hs4[r * 128 + l + 32 * jj];
            #pragma unroll
            for (int oi = 0; oi < 2; oi++) {
                acc[r][oi] += e4[oi][jj].x * h4.x + e4[oi][jj].y * h4.y
                            + e4[oi][jj].z * h4.z + e4[oi][jj].w * h4.w;
            }
        }
    }

    #pragma unroll
    for (int oi = 0; oi < 2; oi++) {
        #pragma unroll
        for (int r = 0; r < 8; r++) {
            float s = warpSum(acc[r][oi]);
            if (l == 0 && oval[oi]) {
                int o = olist[oi];
                int v = v0 + r;
                if (o < 256)      g_logit[v * VOCAB + o] = s;
                else if (o < 320) g_q[v * A + (o - 256)] = s + bias[oi];
                else if (o < 384) g_kT[(o - 320) * VOCAB + v] = s + bias[oi];
                else              g_gate[v] = 1.f / (1.f + __expf(-(s + bias[oi])));
            }
        }
    }
}

// ---------------- k_sm: vocab softmax + score row per qv ------------------
__global__ void __launch_bounds__(256)
k_sm() {
    int qv = blockIdx.x, tid = threadIdx.x;
    __shared__ float red[8];
    __shared__ float qs[A];
    float lo = g_logit[qv * VOCAB + tid];
    if (tid < A) qs[tid] = g_q[qv * A + tid];
    __syncthreads();                 // qs visible to ALL warps before reading
    float s = 0.f;
    #pragma unroll
    for (int d = 0; d < A; d++) s += qs[d] * g_kT[d * VOCAB + tid];
    g_score[qv * VOCAB + tid] = s * 0.125f;
    float m = blockMax256(lo, red);
    float e = __expf(lo - m);
    float Z = blockSum256(e, red);
    g_vprob[qv * VOCAB + tid] = e * __frcp_rn(Z);
}

// ---------------- k_write: AT/LM compute + streaming writer ---------------
__global__ void __launch_bounds__(256)
k_write(const int* __restrict__ tokens, const int* __restrict__ plen,
        float* __restrict__ out, int has_gate, int has_attn) {
    int b = blockIdx.y, t0 = blockIdx.x * 16, tid = threadIdx.x;
    int w = tid >> 5, l = tid & 31;
    __shared__ __align__(16) int toks[LL];
    __shared__ float lut[16][VOCAB];
    __shared__ float scnt[VOCAB];
    __shared__ int qvs[16];

    scnt[tid] = g_cnt[b * VOCAB + tid];
    const int4* tg = (const int4*)(tokens + b * LL);
    int4* ts = (int4*)toks;
    ts[tid] = tg[tid];
    ts[tid + 256] = tg[tid + 256];
    __syncthreads();
    if (tid < 16) qvs[tid] = toks[t0 + tid] & 255;
    __syncthreads();

    // ---- AT rows: warp w computes rows w and w+8 (shuffles only) ----
    #pragma unroll
    for (int jj = 0; jj < 2; jj++) {
        int j = w + jj * 8;
        int qv = qvs[j];
        float sv[8], cf[8];
        float mx = -1e30f;
        #pragma unroll
        for (int m = 0; m < 8; m++) {
            int v = l + 32 * m;
            sv[m] = g_score[qv * VOCAB + v];
            cf[m] = scnt[v];
            mx = fmaxf(mx, cf[m] > 0.f ? sv[m] : -1e30f);
        }
        mx = warpMax(mx);
        float ex[8], z = 0.f;
        #pragma unroll
        for (int m = 0; m < 8; m++) {
            ex[m] = __expf(sv[m] - mx);
            z += cf[m] * ex[m];
        }
        z = warpSum(z);
        float invz = __frcp_rn(z);
        #pragma unroll
        for (int m = 0; m < 8; m++) {
            int v = l + 32 * m;
            float at = ex[m] * invz;
            if (v == 0) at = 0.f;            // PAD column masked
            lut[j][v] = at;
        }
    }
    __syncthreads();

    int P = plen[b];
    float* out_lm   = out;
    float* out_gate = out + (size_t)BB * LL * VOCAB;
    float* out_attn = out_gate + (size_t)BB * LL;

    if (has_gate && tid < 16) out_gate[b * LL + t0 + tid] = g_gate[qvs[tid]];

    // ---- LM: thread = column, 16 rows ----
    float cn = scnt[tid];
    #pragma unroll
    for (int j = 0; j < 16; j++) {
        int qv = qvs[j];
        float gt = g_gate[qv];
        float pv = g_vprob[qv * VOCAB + tid];
        float mixed = gt * pv + (1.f - gt) * (cn * lut[j][tid]);
        __stcs(out_lm + ((size_t)(b * LL + t0 + j)) * VOCAB + tid,
               __logf(fmaxf(mixed, 1e-12f)));
    }

    // ---- attn streaming ----
    if (has_attn) {
        #pragma unroll
        for (int j = 0; j < 16; j++) {
            float4* orow = (float4*)(out_attn + ((size_t)(b * LL + t0 + j)) * LL);
            #pragma unroll
            for (int k2 = 0; k2 < 2; k2++) {
                int sb = (k2 * 256 + tid) * 4;
                int4 tk = *(const int4*)&toks[sb];
                float4 o;
                o.x = (sb + 0 < P) ? lut[j][tk.x & 255] : 0.f;
                o.y = (sb + 1 < P) ? lut[j][tk.y & 255] : 0.f;
                o.z = (sb + 2 < P) ? lut[j][tk.z & 255] : 0.f;
                o.w = (sb + 3 < P) ? lut[j][tk.w & 255] : 0.f;
                __stcs(orow + k2 * 256 + tid, o);
            }
        }
    }
}

// ---------------- launch ----------------
extern "C" void kernel_launch(void* const* d_in, const int* in_sizes, int n_in,
                              void* d_out, int out_size) {
    const int*   tokens = (const int*)d_in[0];
    const int*   plen   = (const int*)d_in[1];
    const float* E      = (const float*)d_in[2];
    const float* en_g   = (const float*)d_in[3];
    const float* en_b   = (const float*)d_in[4];
    const float* fn_g   = (const float*)d_in[5];
    const float* fn_b   = (const float*)d_in[6];
    const float* q_w    = (const float*)d_in[7];
    const float* q_b    = (const float*)d_in[8];
    const float* k_w    = (const float*)d_in[9];
    const float* k_b    = (const float*)d_in[10];
    const float* g_w    = (const float*)d_in[11];
    const float* g_b    = (const float*)d_in[12];

    const long long lm_sz   = (long long)BB * LL * VOCAB;
    const long long gate_sz = (long long)BB * LL;
    const long long attn_sz = (long long)BB * LL * LL;
    int has_gate = (out_size >= lm_sz + gate_sz) ? 1 : 0;
    int has_attn = (out_size >= lm_sz + gate_sz + attn_sz) ? 1 : 0;

    k_tabs <<<8 + 25 * 32, 256>>>(tokens, plen, E, en_g, en_b, fn_g, fn_b,
                                  q_w, q_b, k_w, k_b, g_w, g_b);
    k_sm   <<<VOCAB, 256>>>();
    k_write<<<dim3(LL / 16, BB), 256>>>(tokens, plen, (float*)d_out, has_gate, has_attn);
}